// round 14
// baseline (speedup 1.0000x reference)
#include <cuda_runtime.h>
#include <stdint.h>

// CTC batch loss, prob-domain forward with lazy biased power-of-2 rescaling.
// Warp-specialized (one CTA of 64 threads per batch element):
//   warp 1 (producer): cp.async raw rows gmem->smem ring (64 rows, 16 groups)
//     and compacts each block's label/blank probs (eps + f32x2 pack) into a
//     4-slot compact ring with a TWO-BLOCK LEAD: at iteration g it compacts
//     block g+2, so the conflicted gather never sits on the barrier critical
//     path (R13's mistake), and bar #g publishes compact blocks <= g+2.
//   warp 0 (consumer): per row 2 conflict-free LDS (v2.u64 + 8B broadcast),
//     then the recurrence (f32x2 packed alphas, cross-step pipelined halo
//     SHFL, double-buffered blocks, lazy fold-rescale).
// R14 fixes vs R13:
//   * producer issues group g+kS-1 (16..142) — R13 issued g+kS and NEVER
//     issued group 16 (stale block 16 -> rel_err 6e-4; same class as R10).
//   * make_compact runs with a 2-block lead (cp_wait<kS-4> guarantees raw
//     groups 0..g+2 resident), off the barrier path.

namespace {
constexpr int kB = 256, kT = 512, kC = 256, kL = 128;
constexpr int kBlank = kC - 1;          // 255
constexpr float kEps = 1e-7f;
constexpr int kDepth = 64;              // raw ring rows (power of 2)
constexpr int kGroup = 4;               // rows per commit group = steps per block
constexpr int kNG    = kT / kGroup;     // 128 groups
constexpr int kS     = kDepth / kGroup; // 16 raw ring slots
// smem layout (dynamic): raw ring | qq compact | pbb compact
constexpr int kRawBytes = kDepth * kC * 4;              // 65536
constexpr int kQqOff    = kRawBytes;
constexpr int kQqBytes  = 4 * kGroup * 32 * 16;         // 8192
constexpr int kPbbOff   = kQqOff + kQqBytes;
constexpr int kPbbBytes = 4 * kGroup * 8;               // 128
constexpr int kSmemBytes = kPbbOff + kPbbBytes;         // 73856

using ull = unsigned long long;

__device__ __forceinline__ void cp_async16(uint32_t saddr, const float* g) {
    asm volatile("cp.async.cg.shared.global [%0], [%1], 16;" :: "r"(saddr), "l"(g));
}
__device__ __forceinline__ void cp_commit() {
    asm volatile("cp.async.commit_group;" ::: "memory");
}
template <int N>
__device__ __forceinline__ void cp_wait() {
    asm volatile("cp.async.wait_group %0;" :: "n"(N) : "memory");
}
__device__ __forceinline__ uint32_t redux_max_u32(uint32_t v) {
    uint32_t r;
    asm volatile("redux.sync.max.u32 %0, %1, 0xffffffff;" : "=r"(r) : "r"(v));
    return r;
}
// f32x2 packed helpers
__device__ __forceinline__ ull pk2(float lo, float hi) {
    ull r;
    asm("mov.b64 %0, {%1, %2};" : "=l"(r) : "r"(__float_as_uint(lo)), "r"(__float_as_uint(hi)));
    return r;
}
__device__ __forceinline__ void unpk2(ull v, float& lo, float& hi) {
    uint32_t l, h;
    asm("mov.b64 {%0, %1}, %2;" : "=r"(l), "=r"(h) : "l"(v));
    lo = __uint_as_float(l); hi = __uint_as_float(h);
}
__device__ __forceinline__ float lo2(ull v) {
    uint32_t l, h;
    asm("mov.b64 {%0, %1}, %2;" : "=r"(l), "=r"(h) : "l"(v));
    return __uint_as_float(l);
}
__device__ __forceinline__ ull add2(ull a, ull b) {
    ull r; asm("add.rn.f32x2 %0, %1, %2;" : "=l"(r) : "l"(a), "l"(b)); return r;
}
__device__ __forceinline__ ull mul2(ull a, ull b) {
    ull r; asm("mul.rn.f32x2 %0, %1, %2;" : "=l"(r) : "l"(a), "l"(b)); return r;
}
__device__ __forceinline__ ull fma2(ull a, ull b, ull c) {
    ull r; asm("fma.rn.f32x2 %0, %1, %2, %3;" : "=l"(r) : "l"(a), "l"(b), "l"(c)); return r;
}

struct RowP { ull pbb, q13, q57; float pb; };
} // namespace

__global__ void __launch_bounds__(64) ctc_loss_kernel(
    const int* __restrict__ y_true,     // [B, L] int32, values in [0, C-2]
    const float* __restrict__ y_pred,   // [B, T, C] float32 probabilities
    float* __restrict__ out)            // [B] float32 loss
{
    extern __shared__ __align__(16) float sm[];

    const int b  = blockIdx.x;
    const int w  = threadIdx.x >> 5;    // 0 = consumer, 1 = producer
    const int ln = threadIdx.x & 31;

    const uint32_t smem_u32 = (uint32_t)__cvta_generic_to_shared(sm);
    const uint32_t qq_base  = smem_u32 + kQqOff;
    const uint32_t pbb_base = smem_u32 + kPbbOff;

    // --- labels owned by lane ln (needed by BOTH warps) ---
    const int4 lab4 = reinterpret_cast<const int4*>(y_true + (size_t)b * kL)[ln];
    const int lab0 = lab4.x, lab1 = lab4.y, lab2 = lab4.z, lab3 = lab4.w;
    const ull eps2 = pk2(kEps, kEps);

    if (w == 1) {
        // ================= PRODUCER WARP =================
        const float*   gbase = y_pred + (size_t)b * kT * kC + ln * 8;
        const uint32_t sraw  = smem_u32 + (uint32_t)ln * 32u;

        auto issue_group = [&](int g) {
            if (g < kNG) {
#pragma unroll
                for (int j = 0; j < kGroup; j++) {
                    int r = g * kGroup + j;
                    uint32_t sa = sraw + (uint32_t)(r & (kDepth - 1)) * (kC * 4);
                    const float* ga = gbase + (size_t)r * kC;
                    cp_async16(sa, ga);
                    cp_async16(sa + 16, ga + 4);
                }
            }
            cp_commit();                // always commit: wait_group count invariant
        };

        // raw group g -> compact slot g%4 (eps + f32x2 pack; bit-identical to
        // the consumer-side gather it replaces)
        auto make_compact = [&](int g) {
            int slot = g & 3;
#pragma unroll
            for (int j = 0; j < kGroup; j++) {
                const float* row = sm + ((g * kGroup + j) & (kDepth - 1)) * kC;
                ull q13 = add2(pk2(row[lab0], row[lab1]), eps2);
                ull q57 = add2(pk2(row[lab2], row[lab3]), eps2);
                uint32_t a = qq_base + (uint32_t)(slot * 2048 + j * 512 + ln * 16);
                asm volatile("st.shared.v2.u64 [%0], {%1, %2};"
                             :: "r"(a), "l"(q13), "l"(q57));
            }
            if (ln < kGroup) {
                const float* row = sm + ((g * kGroup + ln) & (kDepth - 1)) * kC;
                float pbv = row[kBlank] + kEps;
                ull pp = pk2(pbv, pbv);
                uint32_t a = pbb_base + (uint32_t)(slot * 32 + ln * 8);
                asm volatile("st.shared.u64 [%0], %1;" :: "r"(a), "l"(pp));
            }
        };

        for (int g = 0; g < kS; g++) issue_group(g);   // groups 0..15 (16 commits)
        cp_wait<kS - 4>();              // pending<=12 -> >=4 complete -> raw 0..3
        make_compact(0);
        make_compact(1);
        make_compact(2);
        __syncthreads();                // bar #0: compact 0..2 published
#pragma unroll 1
        for (int g = 1; g < kNG; g++) {
            // commits before wait: kS + (g-1); pending <= kS-4 -> >= g+3
            // complete -> raw groups 0..g+2 resident.
            cp_wait<kS - 4>();
            if (g + 2 < kNG) make_compact(g + 2);      // 2-block lead
            __syncthreads();            // bar #g: compact <= g+2 published
            // group g+kS-1 (16..142, no gaps) -> slot (g-1)%kS; raw group g-1
            // was last read by make_compact(g-1) at iteration g-3: safe.
            issue_group(g + kS - 1);
        }
        return;                         // bars: 1 + 127 = 128 (matches consumer)
    }

    // ================= CONSUMER WARP =================
    const int labm1 = __shfl_up_sync(0xffffffffu, lab3, 1);
    // skip for odd state s=2m+1: allowed iff s>=2 and label[m] != label[m-1]
    const float sk0f = (ln > 0 && lab0 != labm1) ? 1.f : 0.f;
    const ull sk01 = pk2(sk0f, (lab1 != lab0) ? 1.f : 0.f);
    const ull sk23 = pk2((lab2 != lab1) ? 1.f : 0.f, (lab3 != lab2) ? 1.f : 0.f);

    // alphas: e01=(a0,a2) e23=(a4,a6) o01=(a1,a3) o23=(a5,a7); a8 = state 256
    ull e01 = 0, e23 = 0, o01 = 0, o23 = 0;
    float a1f = 0.f, a3f = 0.f, a5f = 0.f, a7f = 0.f;
    float a8 = 0.f;
    int   E = 0;                        // true_alpha = stored * 2^E
    float pendSc = 1.f;
    int   pendE = 0;
    int   curSexp = 0;

    RowP PA[kGroup], PB[kGroup];

    auto load_compact = [&](int g, RowP* P) {          // conflict-free LDS only
        int slot = g & 3;
#pragma unroll
        for (int j = 0; j < kGroup; j++) {
            ull q13, q57, pp;
            uint32_t a = qq_base + (uint32_t)(slot * 2048 + j * 512 + ln * 16);
            asm volatile("ld.shared.v2.u64 {%0, %1}, [%2];"
                         : "=l"(q13), "=l"(q57) : "r"(a));
            uint32_t ap = pbb_base + (uint32_t)(slot * 32 + j * 8);
            asm volatile("ld.shared.u64 %0, [%1];" : "=l"(pp) : "r"(ap));
            P[j].q13 = q13; P[j].q57 = q57; P[j].pbb = pp; P[j].pb = lo2(pp);
        }
    };

    // Pipelined step: h1 = alpha_{t-1}[8*ln-1] (previous step's shfl).
    auto step = [&](const RowP& r, float h1) -> float {
        // phase 1 (h1-independent)
        ull sodd23 = pk2(a3f, a5f);
        ull in23   = fma2(sk23, sodd23, e23);
        ull ne23   = mul2(add2(e23, sodd23), r.pbb);
        ull no23   = mul2(add2(o23, in23), r.q57);
        float na5, na7;
        unpk2(no23, na5, na7);
        float h1n = __shfl_up_sync(0xffffffffu, na7, 1);  // halo for step t+1
        if (ln == 0) h1n = 0.f;
        // phase 2 (uses h1)
        float na8 = (a8 + a7f) * r.pb;
        ull sodd01 = pk2(h1, a1f);
        ull in01   = fma2(sk01, sodd01, e01);
        ull ne01   = mul2(add2(e01, sodd01), r.pbb);
        ull no01   = mul2(add2(o01, in01), r.q13);
        float na1, na3;
        unpk2(no01, na1, na3);
        e01 = ne01; e23 = ne23; o01 = no01; o23 = no23;
        a1f = na1; a3f = na3; a5f = na5; a7f = na7; a8 = na8;
        return h1n;
    };

    // Lazy biased rescale folded into the block's first-row probabilities
    // (power-of-2 scale -> bit-identical to scaling the alphas directly).
    auto rescale_fold = [&](RowP* P) {
        ull sc2 = pk2(pendSc, pendSc);
        P[0].pbb = mul2(P[0].pbb, sc2);
        P[0].q13 = mul2(P[0].q13, sc2);
        P[0].q57 = mul2(P[0].q57, sc2);
        P[0].pb *= pendSc;
        E += pendE;
        float x0, x1, x2, x3;
        unpk2(e01, x0, x1); unpk2(e23, x2, x3);
        float m = fmaxf(fmaxf(fmaxf(x0, x1), fmaxf(x2, x3)),
                        fmaxf(fmaxf(a1f, a3f), fmaxf(a5f, fmaxf(a7f, a8))));
        uint32_t mm = redux_max_u32(__float_as_uint(m));
        int eb   = (int)(mm >> 23);
        int sexp = 227 - eb - curSexp;      // next max -> 2^100
        if (sexp > 127)  sexp = 127;
        if (sexp < -126) sexp = -126;
        pendSc  = __int_as_float((uint32_t)(sexp + 127) << 23);
        pendE   = -sexp;
        curSexp = sexp;
    };

    __syncthreads();                     // bar #0: compact 0..2 ready
    load_compact(0, PA);                 // block 0
    load_compact(1, PB);                 // block 1

    // ---- block 0: t=0 init + steps 1..3 ----
    if (ln == 0) {
        e01 = pk2(PA[0].pb, 0.f);        // alpha0[0] = p_blank
        float q1lo = lo2(PA[0].q13);
        o01 = pk2(q1lo, 0.f);            // alpha0[1] = p_label0
        a1f = q1lo;
    }
    float h1 = 0.f;                      // alpha0[8*ln-1] = 0 on every lane
    h1 = step(PA[1], h1);
    h1 = step(PA[2], h1);
    h1 = step(PA[3], h1);

    // ---- blocks 1..126, ping-pong buffers, load one block ahead ----
#pragma unroll 1
    for (int g = 1; g < 127; g += 2) {
        rescale_fold(PB);
        __syncthreads();                 // bar #g: compact g+1 published earlier
        load_compact(g + 1, PA);
        h1 = step(PB[0], h1);
        h1 = step(PB[1], h1);
        h1 = step(PB[2], h1);
        h1 = step(PB[3], h1);
        rescale_fold(PA);
        __syncthreads();                 // bar #g+1
        load_compact(g + 2, PB);
        h1 = step(PA[0], h1);
        h1 = step(PA[1], h1);
        h1 = step(PA[2], h1);
        h1 = step(PA[3], h1);
    }

    // ---- tail: block 127 (data in PB) ----
    rescale_fold(PB);
    __syncthreads();                     // bar #127 (matches producer)
    h1 = step(PB[0], h1);
    h1 = step(PB[1], h1);
    h1 = step(PB[2], h1);
    h1 = step(PB[3], h1);

    // loss = -log(alpha[256] + alpha[255]); both live on lane 31.
    if (ln == 31) {
        float tot = a8 + a7f;
        out[b] = -(logf(tot) + (float)E * 0.6931471805599453f);
    }
}

extern "C" void kernel_launch(void* const* d_in, const int* in_sizes, int n_in,
                              void* d_out, int out_size) {
    const int* y_true;
    const float* y_pred;
    if (in_sizes[0] == kB * kL) {
        y_true = (const int*)d_in[0];
        y_pred = (const float*)d_in[1];
    } else {
        y_true = (const int*)d_in[1];
        y_pred = (const float*)d_in[0];
    }
    (void)n_in; (void)out_size;
    cudaFuncSetAttribute(ctc_loss_kernel,
                         cudaFuncAttributeMaxDynamicSharedMemorySize, kSmemBytes);
    ctc_loss_kernel<<<kB, 64, kSmemBytes>>>(y_true, y_pred, (float*)d_out);
}

// round 15
// speedup vs baseline: 1.7449x; 1.7449x over previous
#include <cuda_runtime.h>
#include <stdint.h>

// CTC batch loss, prob-domain forward with lazy biased power-of-2 rescaling.
// Structure = R12 (best, 26.7us): warp-specialized CTA of 64 threads per batch
// element; producer warp cp.asyncs raw rows into a 64-row smem ring; consumer
// warp gathers label/blank probs itself (20 LDS/block) and runs the recurrence
// (f32x2 packed alphas, cross-step pipelined halo SHFL, double-buffered
// blocks, lazy fold-rescale). R13/R14's producer-side gather reverted: the
// producer's serialized LDGSTS(rt8)+LDS stream made it the barrier long pole.
// R15 change: ROLE ASSIGNMENT BY BID RANGE. Classic placement co-locates bids
// x and x+148 on one SM; with consumer always = warp 0, both consumers shared
// SMSP0 (2x154 issue slots/block) while SMSP1 idled. Now bid<148 -> consumer
// = warp 0, bid>=148 -> consumer = warp 1, so each SMSP gets one consumer +
// one producer (~214 slots). Pure scheduling change: bit-identical math.

namespace {
constexpr int kB = 256, kT = 512, kC = 256, kL = 128;
constexpr int kBlank = kC - 1;          // 255
constexpr float kEps = 1e-7f;
constexpr int kDepth = 64;              // raw ring rows (power of 2)
constexpr int kGroup = 4;               // rows per commit group = steps per block
constexpr int kNG    = kT / kGroup;     // 128 groups
constexpr int kS     = kDepth / kGroup; // 16 ring slots
constexpr int kSmemBytes = kDepth * kC * 4;   // 64 KB dynamic

using ull = unsigned long long;

__device__ __forceinline__ void cp_async16(uint32_t saddr, const float* g) {
    asm volatile("cp.async.cg.shared.global [%0], [%1], 16;" :: "r"(saddr), "l"(g));
}
__device__ __forceinline__ void cp_commit() {
    asm volatile("cp.async.commit_group;" ::: "memory");
}
template <int N>
__device__ __forceinline__ void cp_wait() {
    asm volatile("cp.async.wait_group %0;" :: "n"(N) : "memory");
}
__device__ __forceinline__ uint32_t redux_max_u32(uint32_t v) {
    uint32_t r;
    asm volatile("redux.sync.max.u32 %0, %1, 0xffffffff;" : "=r"(r) : "r"(v));
    return r;
}
// f32x2 packed helpers (bit-level pack/unpack are register moves)
__device__ __forceinline__ ull pk2(float lo, float hi) {
    ull r;
    asm("mov.b64 %0, {%1, %2};" : "=l"(r) : "r"(__float_as_uint(lo)), "r"(__float_as_uint(hi)));
    return r;
}
__device__ __forceinline__ void unpk2(ull v, float& lo, float& hi) {
    uint32_t l, h;
    asm("mov.b64 {%0, %1}, %2;" : "=r"(l), "=r"(h) : "l"(v));
    lo = __uint_as_float(l); hi = __uint_as_float(h);
}
__device__ __forceinline__ ull add2(ull a, ull b) {
    ull r; asm("add.rn.f32x2 %0, %1, %2;" : "=l"(r) : "l"(a), "l"(b)); return r;
}
__device__ __forceinline__ ull mul2(ull a, ull b) {
    ull r; asm("mul.rn.f32x2 %0, %1, %2;" : "=l"(r) : "l"(a), "l"(b)); return r;
}
__device__ __forceinline__ ull fma2(ull a, ull b, ull c) {
    ull r; asm("fma.rn.f32x2 %0, %1, %2, %3;" : "=l"(r) : "l"(a), "l"(b), "l"(c)); return r;
}

struct RowP { ull pbb, q13, q57; float pb; };
} // namespace

__global__ void __launch_bounds__(64) ctc_loss_kernel(
    const int* __restrict__ y_true,     // [B, L] int32, values in [0, C-2]
    const float* __restrict__ y_pred,   // [B, T, C] float32 probabilities
    float* __restrict__ out)            // [B] float32 loss
{
    extern __shared__ __align__(16) float ring[];      // [kDepth][kC], 64 KB

    const int b  = blockIdx.x;
    const int w  = threadIdx.x >> 5;
    const int ln = threadIdx.x & 31;

    // Role by bid range: co-resident CTAs are (x, x+148) under classic
    // placement, so this puts one consumer + one producer on each SMSP.
    const int prodW = (b >= 148) ? 0 : 1;

    if (w == prodW) {
        // ================= PRODUCER WARP =================
        const float*   gbase = y_pred + (size_t)b * kT * kC + ln * 8;
        const uint32_t sbase = (uint32_t)__cvta_generic_to_shared(ring)
                             + (uint32_t)ln * 32u;
        auto issue_group = [&](int g) {
            if (g < kNG) {
#pragma unroll
                for (int j = 0; j < kGroup; j++) {
                    int r = g * kGroup + j;
                    uint32_t sa = sbase + (uint32_t)(r & (kDepth - 1)) * (kC * 4);
                    const float* ga = gbase + (size_t)r * kC;
                    cp_async16(sa, ga);
                    cp_async16(sa + 16, ga + 4);
                }
            }
            cp_commit();                // always commit: wait_group count invariant
        };

        for (int g = 0; g < kS; g++) issue_group(g);   // groups 0..15 (16 commits)
        cp_wait<kS - 2>();              // >=2 complete -> groups 0,1 resident
        __syncthreads();                // bar #0
#pragma unroll 1
        for (int g = 1; g < kNG; g++) {
            // commits before this bar: kS + (g-1); <= kS-3 pending
            // -> >= g+2 complete -> groups 0..g+1 resident for consumer.
            cp_wait<kS - 3>();
            __syncthreads();            // bar #g
            // group g+kS-1 (16..142, no gaps) -> slot (g-1)%kS: consumer last
            // read it at bar #(g-2).
            issue_group(g + kS - 1);
        }
        return;                         // bars: 1 + 127 = 128 (matches consumer)
    }

    // ================= CONSUMER WARP =================
    // --- labels owned by this lane: indices 4*ln .. 4*ln+3 ---
    const int4 lab4 = reinterpret_cast<const int4*>(y_true + (size_t)b * kL)[ln];
    const int lab0 = lab4.x, lab1 = lab4.y, lab2 = lab4.z, lab3 = lab4.w;
    const int labm1 = __shfl_up_sync(0xffffffffu, lab3, 1);

    // skip for odd state s=2m+1: allowed iff s>=2 and label[m] != label[m-1]
    const float sk0f = (ln > 0 && lab0 != labm1) ? 1.f : 0.f;
    const ull sk01 = pk2(sk0f, (lab1 != lab0) ? 1.f : 0.f);
    const ull sk23 = pk2((lab2 != lab1) ? 1.f : 0.f, (lab3 != lab2) ? 1.f : 0.f);
    const ull eps2 = pk2(kEps, kEps);

    // alphas: e01=(a0,a2) e23=(a4,a6) o01=(a1,a3) o23=(a5,a7); a8 = state 256
    ull e01 = 0, e23 = 0, o01 = 0, o23 = 0;
    float a1f = 0.f, a3f = 0.f, a5f = 0.f, a7f = 0.f;
    float a8 = 0.f;
    int   E = 0;                        // true_alpha = stored * 2^E
    float pendSc = 1.f;                 // scale folded into the NEXT block's first row
    int   pendE = 0;
    int   curSexp = 0;

    RowP PA[kGroup], PB[kGroup];

    auto gather = [&](int t_base, RowP* P) {   // t_base is a ROW index
#pragma unroll
        for (int j = 0; j < kGroup; j++) {
            const float* row = ring + ((t_base + j) & (kDepth - 1)) * kC;
            float pbv = row[kBlank] + kEps;
            P[j].q13 = add2(pk2(row[lab0], row[lab1]), eps2);
            P[j].q57 = add2(pk2(row[lab2], row[lab3]), eps2);
            P[j].pbb = pk2(pbv, pbv);
            P[j].pb  = pbv;
        }
    };

    // Pipelined step: h1 = alpha_{t-1}[8*ln-1] (previous step's shfl).
    auto step = [&](const RowP& r, float h1) -> float {
        // phase 1 (h1-independent)
        ull sodd23 = pk2(a3f, a5f);
        ull in23   = fma2(sk23, sodd23, e23);
        ull ne23   = mul2(add2(e23, sodd23), r.pbb);
        ull no23   = mul2(add2(o23, in23), r.q57);
        float na5, na7;
        unpk2(no23, na5, na7);
        float h1n = __shfl_up_sync(0xffffffffu, na7, 1);  // halo for step t+1
        if (ln == 0) h1n = 0.f;
        // phase 2 (uses h1)
        float na8 = (a8 + a7f) * r.pb;
        ull sodd01 = pk2(h1, a1f);
        ull in01   = fma2(sk01, sodd01, e01);
        ull ne01   = mul2(add2(e01, sodd01), r.pbb);
        ull no01   = mul2(add2(o01, in01), r.q13);
        float na1, na3;
        unpk2(no01, na1, na3);
        e01 = ne01; e23 = ne23; o01 = no01; o23 = no23;
        a1f = na1; a3f = na3; a5f = na5; a7f = na7; a8 = na8;
        return h1n;
    };

    // Lazy biased rescale folded into the block's first-row probabilities
    // (power-of-2 scale -> bit-identical to scaling the alphas directly).
    auto rescale_fold = [&](RowP* P) {
        ull sc2 = pk2(pendSc, pendSc);
        P[0].pbb = mul2(P[0].pbb, sc2);
        P[0].q13 = mul2(P[0].q13, sc2);
        P[0].q57 = mul2(P[0].q57, sc2);
        P[0].pb *= pendSc;
        E += pendE;
        float x0, x1, x2, x3;
        unpk2(e01, x0, x1); unpk2(e23, x2, x3);
        float m = fmaxf(fmaxf(fmaxf(x0, x1), fmaxf(x2, x3)),
                        fmaxf(fmaxf(a1f, a3f), fmaxf(a5f, fmaxf(a7f, a8))));
        uint32_t mm = redux_max_u32(__float_as_uint(m));
        int eb   = (int)(mm >> 23);
        int sexp = 227 - eb - curSexp;      // next max -> 2^100
        if (sexp > 127)  sexp = 127;
        if (sexp < -126) sexp = -126;
        pendSc  = __int_as_float((uint32_t)(sexp + 127) << 23);
        pendE   = -sexp;
        curSexp = sexp;
    };

    __syncthreads();                     // bar #0: groups 0,1 resident
    gather(0, PA);                       // rows 0..3 (block 0)
    gather(kGroup, PB);                  // rows 4..7 (block 1)

    // ---- block 0: t=0 init + steps 1..3 ----
    if (ln == 0) {
        float q1lo, q1hi;
        unpk2(PA[0].q13, q1lo, q1hi);
        e01 = pk2(PA[0].pb, 0.f);        // alpha0[0] = p_blank
        o01 = pk2(q1lo, 0.f);            // alpha0[1] = p_label0
        a1f = q1lo;
    }
    float h1 = 0.f;                      // alpha0[8*ln-1] = 0 on every lane
    h1 = step(PA[1], h1);
    h1 = step(PA[2], h1);
    h1 = step(PA[3], h1);

    // ---- blocks 1..126, ping-pong buffers, gather one block ahead ----
#pragma unroll 1
    for (int g = 1; g < 127; g += 2) {
        rescale_fold(PB);
        __syncthreads();                 // bar #g: group g+1 resident
        gather((g + 1) * kGroup, PA);
        h1 = step(PB[0], h1);
        h1 = step(PB[1], h1);
        h1 = step(PB[2], h1);
        h1 = step(PB[3], h1);
        rescale_fold(PA);
        __syncthreads();                 // bar #g+1: group g+2 resident
        gather((g + 2) * kGroup, PB);
        h1 = step(PA[0], h1);
        h1 = step(PA[1], h1);
        h1 = step(PA[2], h1);
        h1 = step(PA[3], h1);
    }

    // ---- tail: block 127 (data in PB) ----
    rescale_fold(PB);
    __syncthreads();                     // bar #127 (matches producer)
    h1 = step(PB[0], h1);
    h1 = step(PB[1], h1);
    h1 = step(PB[2], h1);
    h1 = step(PB[3], h1);

    // loss = -log(alpha[256] + alpha[255]); both live on lane 31.
    if (ln == 31) {
        float tot = a8 + a7f;
        out[b] = -(logf(tot) + (float)E * 0.6931471805599453f);
    }
}

extern "C" void kernel_launch(void* const* d_in, const int* in_sizes, int n_in,
                              void* d_out, int out_size) {
    const int* y_true;
    const float* y_pred;
    if (in_sizes[0] == kB * kL) {
        y_true = (const int*)d_in[0];
        y_pred = (const float*)d_in[1];
    } else {
        y_true = (const int*)d_in[1];
        y_pred = (const float*)d_in[0];
    }
    (void)n_in; (void)out_size;
    cudaFuncSetAttribute(ctc_loss_kernel,
                         cudaFuncAttributeMaxDynamicSharedMemorySize, kSmemBytes);
    ctc_loss_kernel<<<kB, 64, kSmemBytes>>>(y_true, y_pred, (float*)d_out);
}